// round 15
// baseline (speedup 1.0000x reference)
#include <cuda_runtime.h>
#include <cuda_fp16.h>
#include <cstdint>

#define B_  256
#define T_  1024
#define H_  256

#define MT 32       // batch rows per group
#define NT 128      // permuted gate cols per CTA (32 hidden units x 4 gates)
#define NGROUP 8
#define NTILE  8
#define THREADS 288 // 8 compute warps + 1 comm warp

#define WRS 264     // L1 y0-half weight row stride (halfs)
#define BLKB 2560   // bytes per producer block: 32 rows x 80B (ldsm conflict-free)
#define GBUF 20480  // 8 blocks = full 32x256 A tile

// ---- dynamic smem layout (bytes) ----
#define AS_Y     0                      // [3][GBUF] y0 slots (L1)
#define AS_H     61440                  // [2][GBUF] h tiles
#define WS_OFF   102400                 // [NT][WRS] halfs (L1 y0 weights)
#define BIAS_OFF 169984                 // [NT] floats
#define WX_OFF   170496                 // [NT] floats (L0)
#define MBAR_OFF 171008                 // mbarrier block
#define SMEM_TOTAL 171072

// mbar byte offsets within MBAR block (8B each)
#define MB_HTX   0    // h bulk tx: [buf][half] -> 0,8,16,24
#define MB_YTX   32   // y0 bulk tx: [slot] -> 32,40,48

// -------- persistent device scratch --------
// blocked layout: [t][grp][producer][row*40 + unit] halfs (80B rows)
__device__ __align__(16) __half g_y0[T_][NGROUP][NTILE][BLKB / 2];
__device__ __align__(16) __half g_h1[2][NGROUP][NTILE][BLKB / 2];
// counting flags, 128B-strided: 256 thread-releases per step -> 256*(t+1)
__device__ unsigned g_flag[2][NGROUP][NTILE][32];

__global__ void init_kernel() {
    int i = threadIdx.x;
    if (i < 2 * NGROUP * NTILE) ((unsigned*)g_flag)[i * 32] = 0u;
}

// -------- helpers --------
__device__ __forceinline__ uint32_t smem_u32(const void* p) {
    return (uint32_t)__cvta_generic_to_shared(p);
}
__device__ __forceinline__ unsigned ld_acq(const unsigned* p) {
    unsigned v;
    asm volatile("ld.acquire.gpu.global.u32 %0, [%1];" : "=r"(v) : "l"(p) : "memory");
    return v;
}
__device__ __forceinline__ void red_add_rel(unsigned* p) {
    asm volatile("red.release.gpu.global.add.u32 [%0], 1;" :: "l"(p) : "memory");
}
__device__ __forceinline__ float tanh_hw(float x) {
    float y;
    asm("tanh.approx.f32 %0, %1;" : "=f"(y) : "f"(x));
    return y;
}
__device__ __forceinline__ float sig_hw(float x) {
    return fmaf(0.5f, tanh_hw(0.5f * x), 0.5f);
}
__device__ __forceinline__ void mma16816(float* d, const uint32_t* a, uint32_t b0, uint32_t b1) {
    asm volatile(
        "mma.sync.aligned.m16n8k16.row.col.f32.f16.f16.f32 "
        "{%0,%1,%2,%3}, {%4,%5,%6,%7}, {%8,%9}, {%0,%1,%2,%3};\n"
        : "+f"(d[0]), "+f"(d[1]), "+f"(d[2]), "+f"(d[3])
        : "r"(a[0]), "r"(a[1]), "r"(a[2]), "r"(a[3]), "r"(b0), "r"(b1));
}
__device__ __forceinline__ void ldsm4(uint32_t* r, uint32_t addr) {
    asm volatile("ldmatrix.sync.aligned.m8n8.x4.shared.b16 {%0,%1,%2,%3}, [%4];"
        : "=r"(r[0]), "=r"(r[1]), "=r"(r[2]), "=r"(r[3]) : "r"(addr));
}
__device__ __forceinline__ void bulk_g2s(uint32_t dst, const void* src,
                                         uint32_t bytes, uint32_t mbar) {
    asm volatile(
        "cp.async.bulk.shared::cluster.global.mbarrier::complete_tx::bytes "
        "[%0], [%1], %2, [%3];"
        :: "r"(dst), "l"(src), "r"(bytes), "r"(mbar) : "memory");
}
__device__ __forceinline__ void mbar_init(uint32_t a, uint32_t cnt) {
    asm volatile("mbarrier.init.shared.b64 [%0], %1;" :: "r"(a), "r"(cnt) : "memory");
}
__device__ __forceinline__ void mbar_expect(uint32_t a, uint32_t bytes) {
    asm volatile("mbarrier.arrive.expect_tx.shared.b64 _, [%0], %1;"
                 :: "r"(a), "r"(bytes) : "memory");
}
__device__ __forceinline__ void mbar_wait(uint32_t a, uint32_t par) {
    uint32_t done = 0;
    while (!done) {
        asm volatile(
            "{\n\t.reg .pred p;\n\t"
            "mbarrier.try_wait.parity.acquire.cta.shared::cta.b64 p, [%1], %2, 0x989680;\n\t"
            "selp.b32 %0, 1, 0, p;\n\t}"
            : "=r"(done) : "r"(a), "r"(par) : "memory");
    }
}

// ====================================================================
// R12 structure (best baseline, 2997us) with exactly ONE change:
// the h publish is shfl-packed into ONE 8-byte STG per thread.
// After the gate epilogue, 4 shfl.xor(2) exchanges let each lane
// assemble a complete row-quad (units 4w..4w+3 of one row), stored as
// a single aligned uint2 at row*80 + warp*8 — 4x fewer scattered store
// transactions on the critical path before the release.
//   warps 0-7 : compute, zero CTA barriers; per-THREAD red.release
//               (flag target 256*(t+1)) exactly as R12.
//   warp 8    : comm, identical to R12.
// ====================================================================
template <bool IS_L0>
__device__ __forceinline__ void run_layer(const float* __restrict__ x,
                                          const float* __restrict__ Wih,
                                          const float* __restrict__ Whh,
                                          const float* __restrict__ bih,
                                          const float* __restrict__ bhh,
                                          float* __restrict__ out,
                                          int layer_idx) {
    constexpr int L = IS_L0 ? 0 : 1;

    extern __shared__ char sm[];
    const uint32_t smb = smem_u32(sm);
    float*  bias_s = (float*)(sm + BIAS_OFF);
    float*  wx_s   = (float*)(sm + WX_OFF);
    __half* Ws     = (__half*)(sm + WS_OFF);
    const uint32_t MB = smb + MBAR_OFF;

    const int tid  = threadIdx.x;
    const int lane = tid & 31, warp = tid >> 5;
    const int gid  = lane >> 2, tig = lane & 3;
    const int ntile = blockIdx.x, grp = blockIdx.y;
    const int n0 = ntile * NT;
    const int b0 = grp * MT;
    const int j0 = n0 >> 2;

    // ---- mbar init ----
    if (tid == 0) {
        mbar_init(MB + MB_HTX + 0, 1);  mbar_init(MB + MB_HTX + 8, 1);
        mbar_init(MB + MB_HTX + 16, 1); mbar_init(MB + MB_HTX + 24, 1);
        mbar_init(MB + MB_YTX + 0, 1);  mbar_init(MB + MB_YTX + 8, 1);
        mbar_init(MB + MB_YTX + 16, 1);
    }
    __syncthreads();

    // ---- one-time: bias (+ scalar input weight for L0) into smem ----
    if (tid < NT) {
        int n_g = n0 + tid;
        int p   = (n_g & 3) * H_ + (n_g >> 2);
        bias_s[tid] = bih[p] + bhh[p];
        if (IS_L0) wx_s[tid] = Wih[p];
    }

    // ---- one-time: h-half weights (Whh) into registers (compute warps) ----
    uint32_t bw[2][16][2];
    if (warp < 8) {
        #pragma unroll
        for (int ni = 0; ni < 2; ni++) {
            int n_g = n0 + warp * 16 + ni * 8 + gid;
            int p   = (n_g & 3) * H_ + (n_g >> 2);
            const float* wr = Whh + (size_t)p * H_;
            #pragma unroll
            for (int kc = 0; kc < 16; kc++) {
                int k = kc * 16 + tig * 2;
                __half2 h01 = __floats2half2_rn(wr[k], wr[k + 1]);
                __half2 h89 = __floats2half2_rn(wr[k + 8], wr[k + 9]);
                bw[ni][kc][0] = *(uint32_t*)&h01;
                bw[ni][kc][1] = *(uint32_t*)&h89;
            }
        }
    }

    if constexpr (!IS_L0) {
        // y0-half weights (Wih1, K=256) into smem
        for (int idx = tid; idx < NT * H_; idx += THREADS) {
            int nl = idx >> 8, k = idx & 255;
            int n_g = n0 + nl;
            int p   = (n_g & 3) * H_ + (n_g >> 2);
            Ws[nl * WRS + k] = __float2half_rn(Wih[(size_t)p * H_ + k]);
        }
        if (tid == 0) {
            mbar_expect(MB + MB_YTX + 0, GBUF);
            mbar_expect(MB + MB_YTX + 8, GBUF);
        }
    }
    __syncthreads();

    if constexpr (!IS_L0) {
        // prologue: comm warp fetches y0[0] -> slot0, y0[1] -> slot1
        if (warp == 8 && lane < 8) {
            while (ld_acq(&g_flag[0][grp][lane][0]) < (1u << 8)) { }
            bulk_g2s(smb + AS_Y + lane * BLKB, &g_y0[0][grp][lane][0],
                     BLKB, MB + MB_YTX + 0);
            while (ld_acq(&g_flag[0][grp][lane][0]) < (2u << 8)) { }
            bulk_g2s(smb + AS_Y + GBUF + lane * BLKB, &g_y0[1][grp][lane][0],
                     BLKB, MB + MB_YTX + 8);
        }
    }

    // ---- per-lane ldsm byte offset within a blocked A tile ----
    const uint32_t aoffB = (uint32_t)((lane & 15) * 80 + ((lane >> 4) & 1) * 16);
    uint32_t bAddr = 0;
    if constexpr (!IS_L0) {
        int rB = (warp & 7) * 16 + (lane & 7) + ((lane & 16) ? 8 : 0);
        int cB = (lane & 8) ? 8 : 0;
        bAddr = smb + WS_OFF + (uint32_t)((rB * WRS + cB) * 2);
    }

    if (warp < 8) {
        // ================= COMPUTE WARPS =================
        const int r0 = gid + ((tig & 1) << 3);        // row for mi=0 (mi adds 16)
        const int u0 = (warp << 2) + (tig >> 1);      // unit for ni=0 (ni adds 2)

        float4 breg[2], wreg[2];
        #pragma unroll
        for (int ni = 0; ni < 2; ni++) {
            breg[ni] = *(const float4*)(bias_s + 4 * (u0 + 2 * ni));
            if (IS_L0) wreg[ni] = *(const float4*)(wx_s + 4 * (u0 + 2 * ni));
        }
        const float* xr[2];
        if constexpr (IS_L0) {
            xr[0] = x + (size_t)(b0 + r0) * T_;
            xr[1] = x + (size_t)(b0 + r0 + 16) * T_;
        }

        // packed-publish constants: each lane owns one full row-quad
        const int row_out = gid + ((tig & 1) << 3) + ((tig >> 1) << 4);
        const int qoff = row_out * 40 + (warp << 2);   // halfs

        float creg[2][2] = {{0.f, 0.f}, {0.f, 0.f}};
        uint32_t phHT = 0, phY = 0;

        for (int t = 0; t < T_; ++t) {
            const int cb = t & 1, nb = cb ^ 1;
            const int ys = t % 3;
            const uint32_t hbase = smb + AS_H + (uint32_t)cb * GBUF;

            float xv[2];
            if constexpr (IS_L0) { xv[0] = xr[0][t]; xv[1] = xr[1][t]; }

            float acc[2][2][4];
            #pragma unroll
            for (int mi = 0; mi < 2; mi++)
                #pragma unroll
                for (int ni = 0; ni < 2; ni++)
                    #pragma unroll
                    for (int r = 0; r < 4; r++) acc[mi][ni][r] = 0.f;

            // ---- L1: y0-half GEMM (independent of h; hides h bulks) ----
            if constexpr (!IS_L0) {
                mbar_wait(MB + MB_YTX + ys * 8, (phY >> ys) & 1u);
                phY ^= 1u << ys;
                const uint32_t ybase = smb + AS_Y + (uint32_t)ys * GBUF;
                #pragma unroll
                for (int kc = 0; kc < 16; kc++) {
                    uint32_t a0[4], a1[4], bb[4];
                    const uint32_t ad = ybase + (kc >> 1) * BLKB + (kc & 1) * 32 + aoffB;
                    ldsm4(a0, ad);
                    ldsm4(a1, ad + 1280);
                    ldsm4(bb, bAddr + kc * 32u);
                    mma16816(acc[0][0], a0, bb[0], bb[1]);
                    mma16816(acc[0][1], a0, bb[2], bb[3]);
                    mma16816(acc[1][0], a1, bb[0], bb[1]);
                    mma16816(acc[1][1], a1, bb[2], bb[3]);
                }
            }

            // ---- h-half GEMM, two halves overlapped with arrival ----
            if (t > 0) {
                mbar_wait(MB + MB_HTX + cb * 16 + 0, (phHT >> (cb * 2)) & 1u);
                phHT ^= 1u << (cb * 2);
                #pragma unroll
                for (int kc = 0; kc < 8; kc++) {
                    uint32_t a0[4], a1[4];
                    const uint32_t ad = hbase + (kc >> 1) * BLKB + (kc & 1) * 32 + aoffB;
                    ldsm4(a0, ad);
                    ldsm4(a1, ad + 1280);
                    mma16816(acc[0][0], a0, bw[0][kc][0], bw[0][kc][1]);
                    mma16816(acc[0][1], a0, bw[1][kc][0], bw[1][kc][1]);
                    mma16816(acc[1][0], a1, bw[0][kc][0], bw[0][kc][1]);
                    mma16816(acc[1][1], a1, bw[1][kc][0], bw[1][kc][1]);
                }
                mbar_wait(MB + MB_HTX + cb * 16 + 8, (phHT >> (cb * 2 + 1)) & 1u);
                phHT ^= 1u << (cb * 2 + 1);
                #pragma unroll
                for (int kc = 8; kc < 16; kc++) {
                    uint32_t a0[4], a1[4];
                    const uint32_t ad = hbase + (kc >> 1) * BLKB + (kc & 1) * 32 + aoffB;
                    ldsm4(a0, ad);
                    ldsm4(a1, ad + 1280);
                    mma16816(acc[0][0], a0, bw[0][kc][0], bw[0][kc][1]);
                    mma16816(acc[0][1], a0, bw[1][kc][0], bw[1][kc][1]);
                    mma16816(acc[1][0], a1, bw[0][kc][0], bw[0][kc][1]);
                    mma16816(acc[1][1], a1, bw[1][kc][0], bw[1][kc][1]);
                }
            }

            // ---- shfl epilogue: pair-exchange gates, compute cells ----
            float hv[2][2];
            #pragma unroll
            for (int mi = 0; mi < 2; mi++) {
                #pragma unroll
                for (int ni = 0; ni < 2; ni++) {
                    float sa = (tig & 1) ? acc[mi][ni][0] : acc[mi][ni][2];
                    float sb = (tig & 1) ? acc[mi][ni][1] : acc[mi][ni][3];
                    float ra = __shfl_xor_sync(0xffffffffu, sa, 1, 32);
                    float rb = __shfl_xor_sync(0xffffffffu, sb, 1, 32);
                    float pi, pf, pg, po;
                    if (tig & 1) { pi = ra;            pf = rb;
                                   pg = acc[mi][ni][2]; po = acc[mi][ni][3]; }
                    else         { pi = acc[mi][ni][0]; pf = acc[mi][ni][1];
                                   pg = ra;             po = rb; }
                    pi += breg[ni].x; pf += breg[ni].y;
                    pg += breg[ni].z; po += breg[ni].w;
                    if constexpr (IS_L0) {
                        pi += xv[mi] * wreg[ni].x;
                        pf += xv[mi] * wreg[ni].y;
                        pg += xv[mi] * wreg[ni].z;
                        po += xv[mi] * wreg[ni].w;
                    }
                    float ig = sig_hw(pi), fg = sig_hw(pf);
                    float gg = tanh_hw(pg), og = sig_hw(po);
                    float c  = fg * creg[mi][ni] + ig * gg;
                    creg[mi][ni] = c;
                    float h  = og * tanh_hw(c);
                    hv[mi][ni] = h;

                    if (t == T_ - 1) {
                        const int row = r0 + 16 * mi;
                        const int u   = u0 + 2 * ni;
                        size_t oidx = ((size_t)layer_idx * B_ + (b0 + row)) * H_ + j0 + u;
                        out[oidx] = h;
                        out[(size_t)2 * B_ * H_ + oidx] = c;
                    }
                }
            }

            // ---- packed publish: ONE 8B STG per thread ----
            // exchange across tig bit1 (lane^2): partner holds the odd
            // units (w4+1, w4+3) of the same rows.
            {
                float pa0 = __shfl_xor_sync(0xffffffffu, hv[0][0], 2, 32);
                float pb0 = __shfl_xor_sync(0xffffffffu, hv[0][1], 2, 32);
                float pa1 = __shfl_xor_sync(0xffffffffu, hv[1][0], 2, 32);
                float pb1 = __shfl_xor_sync(0xffffffffu, hv[1][1], 2, 32);
                __half2 q0, q1;
                if ((tig >> 1) == 0) {   // owns mi=0 row (r0)
                    q0 = __floats2half2_rn(hv[0][0], pa0);   // units w4+0, w4+1
                    q1 = __floats2half2_rn(hv[0][1], pb0);   // units w4+2, w4+3
                } else {                 // owns mi=1 row (r0+16)
                    q0 = __floats2half2_rn(pa1, hv[1][0]);
                    q1 = __floats2half2_rn(pb1, hv[1][1]);
                }
                uint2 pk = make_uint2(*(uint32_t*)&q0, *(uint32_t*)&q1);
                if constexpr (IS_L0) {
                    *(uint2*)&g_y0[t][grp][ntile][qoff] = pk;
                } else {
                    if (t + 1 < T_)
                        *(uint2*)&g_h1[nb][grp][ntile][qoff] = pk;
                }
            }

            // ---- release: per-thread counting-flag increment (R12) ----
            if (IS_L0 || t + 1 < T_)
                red_add_rel(&g_flag[L][grp][ntile][0]);
        }
    } else {
        // ================= COMM WARP =================
        for (int t = 0; t < T_ - 1; ++t) {
            const int nb = (t + 1) & 1;

            // arm expects for this iteration's bulks (lane 0), then make
            // the whole warp wait so NO lane's bulk can precede them.
            if (lane == 0) {
                mbar_expect(MB + MB_HTX + nb * 16 + 0, GBUF / 2);
                mbar_expect(MB + MB_HTX + nb * 16 + 8, GBUF / 2);
                if (!IS_L0 && t + 2 < T_)
                    mbar_expect(MB + MB_YTX + ((t + 2) % 3) * 8, GBUF);
            }
            __syncwarp();

            // h blocks for step t+1: lane w serves producer w (self-gated:
            // the poll set includes our own CTA's flag at lane == ntile)
            if (lane < 8) {
                while (ld_acq(&g_flag[L][grp][lane][0]) <
                       (unsigned)((t + 1) << 8)) { }
                const void* src = IS_L0 ? (const void*)&g_y0[t][grp][lane][0]
                                        : (const void*)&g_h1[nb][grp][lane][0];
                bulk_g2s(smb + AS_H + (uint32_t)nb * GBUF + lane * BLKB, src,
                         BLKB, MB + MB_HTX + nb * 16 + (lane >> 2) * 8);
            }
            // y0[t+2] prefetch (L1): lanes 8-15 serve producers 0-7
            if (!IS_L0 && lane >= 8 && lane < 16 && t + 2 < T_) {
                const int pw = lane - 8;
                while (ld_acq(&g_flag[0][grp][pw][0]) <
                       (unsigned)((t + 3) << 8)) { }
                bulk_g2s(smb + AS_Y + (uint32_t)((t + 2) % 3) * GBUF + pw * BLKB,
                         &g_y0[t + 2][grp][pw][0], BLKB,
                         MB + MB_YTX + ((t + 2) % 3) * 8);
            }

            // reconverge: the L0-gated y lanes must not outrun the
            // self-gated h lanes into the next iteration (slot reuse safety)
            __syncwarp();
        }
    }
}

__global__ void __launch_bounds__(THREADS, 1)
lstm_fused_kernel(const float* __restrict__ x,
                  const float* __restrict__ Wih0, const float* __restrict__ Whh0,
                  const float* __restrict__ bih0, const float* __restrict__ bhh0,
                  const float* __restrict__ Wih1, const float* __restrict__ Whh1,
                  const float* __restrict__ bih1, const float* __restrict__ bhh1,
                  float* __restrict__ out) {
    if (blockIdx.z == 0)
        run_layer<true >(x, Wih0, Whh0, bih0, bhh0, out, 0);
    else
        run_layer<false>(nullptr, Wih1, Whh1, bih1, bhh1, out, 1);
}

extern "C" void kernel_launch(void* const* d_in, const int* in_sizes, int n_in,
                              void* d_out, int out_size) {
    (void)in_sizes; (void)n_in; (void)out_size;
    const float* x    = (const float*)d_in[0];
    const float* Wih0 = (const float*)d_in[1];
    const float* Whh0 = (const float*)d_in[2];
    const float* bih0 = (const float*)d_in[3];
    const float* bhh0 = (const float*)d_in[4];
    const float* Wih1 = (const float*)d_in[5];
    const float* Whh1 = (const float*)d_in[6];
    const float* bih1 = (const float*)d_in[7];
    const float* bhh1 = (const float*)d_in[8];
    float* out = (float*)d_out;

    cudaFuncSetAttribute((const void*)&lstm_fused_kernel,
                         cudaFuncAttributeMaxDynamicSharedMemorySize, SMEM_TOTAL);

    init_kernel<<<1, 128>>>();

    dim3 grid(NTILE, NGROUP, 2);
    lstm_fused_kernel<<<grid, THREADS, SMEM_TOTAL>>>(
        x, Wih0, Whh0, bih0, bhh0, Wih1, Whh1, bih1, bhh1, out);
}

// round 16
// speedup vs baseline: 1.0705x; 1.0705x over previous
#include <cuda_runtime.h>
#include <cuda_fp16.h>
#include <cstdint>

#define B_  256
#define T_  1024
#define H_  256

#define MT 32       // batch rows per group
#define NT 128      // permuted gate cols per CTA (32 hidden units x 4 gates)
#define NGROUP 8
#define NTILE  8
#define THREADS 320 // 8 compute warps + h-comm warp + y-comm warp

#define WRS 264     // L1 y0-half weight row stride (halfs)
#define BLKB 2560   // bytes per producer block: 32 rows x 80B (ldsm conflict-free)
#define GBUF 20480  // 8 blocks = full 32x256 A tile

// ---- dynamic smem layout (bytes) ----
#define AS_Y     0                      // [3][GBUF] y0 slots (L1)
#define AS_H     61440                  // [2][GBUF] h tiles
#define WS_OFF   102400                 // [NT][WRS] halfs (L1 y0 weights)
#define BIAS_OFF 169984                 // [NT] floats
#define WX_OFF   170496                 // [NT] floats (L0)
#define MBAR_OFF 171008                 // mbarrier block
#define SMEM_TOTAL 171104

// mbar byte offsets within MBAR block (8B each)
// h quarters: buf*32 + q*8  (q = producer pair {2q,2q+1} = kc 4q..4q+3)
#define MB_HTX   0
#define MB_YTX   64   // y0 bulk tx: [slot] -> 64,72,80

// -------- persistent device scratch --------
// blocked layout: [t][grp][producer][row*40 + unit] halfs (80B rows)
__device__ __align__(16) __half g_y0[T_][NGROUP][NTILE][BLKB / 2];
__device__ __align__(16) __half g_h1[2][NGROUP][NTILE][BLKB / 2];
// counting flags, 128B-strided: 256 thread-releases per step -> 256*(t+1)
__device__ unsigned g_flag[2][NGROUP][NTILE][32];

__global__ void init_kernel() {
    int i = threadIdx.x;
    if (i < 2 * NGROUP * NTILE) ((unsigned*)g_flag)[i * 32] = 0u;
}

// -------- helpers --------
__device__ __forceinline__ uint32_t smem_u32(const void* p) {
    return (uint32_t)__cvta_generic_to_shared(p);
}
__device__ __forceinline__ unsigned ld_acq(const unsigned* p) {
    unsigned v;
    asm volatile("ld.acquire.gpu.global.u32 %0, [%1];" : "=r"(v) : "l"(p) : "memory");
    return v;
}
__device__ __forceinline__ void red_add_rel(unsigned* p) {
    asm volatile("red.release.gpu.global.add.u32 [%0], 1;" :: "l"(p) : "memory");
}
__device__ __forceinline__ float tanh_hw(float x) {
    float y;
    asm("tanh.approx.f32 %0, %1;" : "=f"(y) : "f"(x));
    return y;
}
__device__ __forceinline__ float sig_hw(float x) {
    return fmaf(0.5f, tanh_hw(0.5f * x), 0.5f);
}
__device__ __forceinline__ void mma16816(float* d, const uint32_t* a, uint32_t b0, uint32_t b1) {
    asm volatile(
        "mma.sync.aligned.m16n8k16.row.col.f32.f16.f16.f32 "
        "{%0,%1,%2,%3}, {%4,%5,%6,%7}, {%8,%9}, {%0,%1,%2,%3};\n"
        : "+f"(d[0]), "+f"(d[1]), "+f"(d[2]), "+f"(d[3])
        : "r"(a[0]), "r"(a[1]), "r"(a[2]), "r"(a[3]), "r"(b0), "r"(b1));
}
__device__ __forceinline__ void ldsm4(uint32_t* r, uint32_t addr) {
    asm volatile("ldmatrix.sync.aligned.m8n8.x4.shared.b16 {%0,%1,%2,%3}, [%4];"
        : "=r"(r[0]), "=r"(r[1]), "=r"(r[2]), "=r"(r[3]) : "r"(addr));
}
__device__ __forceinline__ void bulk_g2s(uint32_t dst, const void* src,
                                         uint32_t bytes, uint32_t mbar) {
    asm volatile(
        "cp.async.bulk.shared::cluster.global.mbarrier::complete_tx::bytes "
        "[%0], [%1], %2, [%3];"
        :: "r"(dst), "l"(src), "r"(bytes), "r"(mbar) : "memory");
}
__device__ __forceinline__ void mbar_init(uint32_t a, uint32_t cnt) {
    asm volatile("mbarrier.init.shared.b64 [%0], %1;" :: "r"(a), "r"(cnt) : "memory");
}
__device__ __forceinline__ void mbar_expect(uint32_t a, uint32_t bytes) {
    asm volatile("mbarrier.arrive.expect_tx.shared.b64 _, [%0], %1;"
                 :: "r"(a), "r"(bytes) : "memory");
}
__device__ __forceinline__ void mbar_wait(uint32_t a, uint32_t par) {
    uint32_t done = 0;
    while (!done) {
        asm volatile(
            "{\n\t.reg .pred p;\n\t"
            "mbarrier.try_wait.parity.acquire.cta.shared::cta.b64 p, [%1], %2, 0x989680;\n\t"
            "selp.b32 %0, 1, 0, p;\n\t}"
            : "=r"(done) : "r"(a), "r"(par) : "memory");
    }
}

// ====================================================================
// R12 base with two structural changes:
//  (1) comm split: warp 8 = h-comm only; warp 9 = y0 prefetch (L1),
//      self-gated on own-CTA progress — L1's h path is no longer
//      coupled to L0's lead through a shared __syncwarp.
//  (2) h arrival at quarter granularity: 4 tx-mbars per buffer
//      (2 producers / 4 kc each); the h-GEMM starts when the first
//      pair lands and pipelines with the rest — shortens the fully
//      exposed part of L0's exchange chain.
// Everything else (per-thread red.release flags, shfl epilogue,
// scattered publish, bulk pulls) is byte-identical to R12.
// ====================================================================
template <bool IS_L0>
__device__ __forceinline__ void run_layer(const float* __restrict__ x,
                                          const float* __restrict__ Wih,
                                          const float* __restrict__ Whh,
                                          const float* __restrict__ bih,
                                          const float* __restrict__ bhh,
                                          float* __restrict__ out,
                                          int layer_idx) {
    constexpr int L = IS_L0 ? 0 : 1;

    extern __shared__ char sm[];
    const uint32_t smb = smem_u32(sm);
    float*  bias_s = (float*)(sm + BIAS_OFF);
    float*  wx_s   = (float*)(sm + WX_OFF);
    __half* Ws     = (__half*)(sm + WS_OFF);
    const uint32_t MB = smb + MBAR_OFF;

    const int tid  = threadIdx.x;
    const int lane = tid & 31, warp = tid >> 5;
    const int gid  = lane >> 2, tig = lane & 3;
    const int ntile = blockIdx.x, grp = blockIdx.y;
    const int n0 = ntile * NT;
    const int b0 = grp * MT;
    const int j0 = n0 >> 2;

    // ---- mbar init: 8 h quarters + 3 y slots ----
    if (tid == 0) {
        #pragma unroll
        for (int i = 0; i < 8; i++) mbar_init(MB + MB_HTX + i * 8, 1);
        mbar_init(MB + MB_YTX + 0, 1);
        mbar_init(MB + MB_YTX + 8, 1);
        mbar_init(MB + MB_YTX + 16, 1);
    }
    __syncthreads();

    // ---- one-time: bias (+ scalar input weight for L0) into smem ----
    if (tid < NT) {
        int n_g = n0 + tid;
        int p   = (n_g & 3) * H_ + (n_g >> 2);
        bias_s[tid] = bih[p] + bhh[p];
        if (IS_L0) wx_s[tid] = Wih[p];
    }

    // ---- one-time: h-half weights (Whh) into registers (compute warps) ----
    uint32_t bw[2][16][2];
    if (warp < 8) {
        #pragma unroll
        for (int ni = 0; ni < 2; ni++) {
            int n_g = n0 + warp * 16 + ni * 8 + gid;
            int p   = (n_g & 3) * H_ + (n_g >> 2);
            const float* wr = Whh + (size_t)p * H_;
            #pragma unroll
            for (int kc = 0; kc < 16; kc++) {
                int k = kc * 16 + tig * 2;
                __half2 h01 = __floats2half2_rn(wr[k], wr[k + 1]);
                __half2 h89 = __floats2half2_rn(wr[k + 8], wr[k + 9]);
                bw[ni][kc][0] = *(uint32_t*)&h01;
                bw[ni][kc][1] = *(uint32_t*)&h89;
            }
        }
    }

    if constexpr (!IS_L0) {
        // y0-half weights (Wih1, K=256) into smem
        for (int idx = tid; idx < NT * H_; idx += THREADS) {
            int nl = idx >> 8, k = idx & 255;
            int n_g = n0 + nl;
            int p   = (n_g & 3) * H_ + (n_g >> 2);
            Ws[nl * WRS + k] = __float2half_rn(Wih[(size_t)p * H_ + k]);
        }
    }
    __syncthreads();

    // ---- per-lane ldsm byte offset within a blocked A tile ----
    const uint32_t aoffB = (uint32_t)((lane & 15) * 80 + ((lane >> 4) & 1) * 16);
    uint32_t bAddr = 0;
    if constexpr (!IS_L0) {
        int rB = (warp & 7) * 16 + (lane & 7) + ((lane & 16) ? 8 : 0);
        int cB = (lane & 8) ? 8 : 0;
        bAddr = smb + WS_OFF + (uint32_t)((rB * WRS + cB) * 2);
    }

    if (warp < 8) {
        // ================= COMPUTE WARPS =================
        const int r0 = gid + ((tig & 1) << 3);        // row for mi=0 (mi adds 16)
        const int u0 = (warp << 2) + (tig >> 1);      // unit for ni=0 (ni adds 2)

        float4 breg[2], wreg[2];
        #pragma unroll
        for (int ni = 0; ni < 2; ni++) {
            breg[ni] = *(const float4*)(bias_s + 4 * (u0 + 2 * ni));
            if (IS_L0) wreg[ni] = *(const float4*)(wx_s + 4 * (u0 + 2 * ni));
        }
        const float* xr[2];
        if constexpr (IS_L0) {
            xr[0] = x + (size_t)(b0 + r0) * T_;
            xr[1] = x + (size_t)(b0 + r0 + 16) * T_;
        }

        float creg[2][2] = {{0.f, 0.f}, {0.f, 0.f}};
        uint32_t phHT = 0, phY = 0;

        for (int t = 0; t < T_; ++t) {
            const int cb = t & 1, nb = cb ^ 1;
            const int ys = t % 3;
            const uint32_t hbase = smb + AS_H + (uint32_t)cb * GBUF;

            float xv[2];
            if constexpr (IS_L0) { xv[0] = xr[0][t]; xv[1] = xr[1][t]; }

            float acc[2][2][4];
            #pragma unroll
            for (int mi = 0; mi < 2; mi++)
                #pragma unroll
                for (int ni = 0; ni < 2; ni++)
                    #pragma unroll
                    for (int r = 0; r < 4; r++) acc[mi][ni][r] = 0.f;

            // ---- L1: y0-half GEMM (independent of h; hides h bulks) ----
            if constexpr (!IS_L0) {
                mbar_wait(MB + MB_YTX + ys * 8, (phY >> ys) & 1u);
                phY ^= 1u << ys;
                const uint32_t ybase = smb + AS_Y + (uint32_t)ys * GBUF;
                #pragma unroll
                for (int kc = 0; kc < 16; kc++) {
                    uint32_t a0[4], a1[4], bb[4];
                    const uint32_t ad = ybase + (kc >> 1) * BLKB + (kc & 1) * 32 + aoffB;
                    ldsm4(a0, ad);
                    ldsm4(a1, ad + 1280);
                    ldsm4(bb, bAddr + kc * 32u);
                    mma16816(acc[0][0], a0, bb[0], bb[1]);
                    mma16816(acc[0][1], a0, bb[2], bb[3]);
                    mma16816(acc[1][0], a1, bb[0], bb[1]);
                    mma16816(acc[1][1], a1, bb[2], bb[3]);
                }
            }

            // ---- h-GEMM: 4 quarters, pipelined with producer arrival ----
            if (t > 0) {
                #pragma unroll
                for (int q = 0; q < 4; q++) {
                    const int pb = cb * 4 + q;
                    mbar_wait(MB + MB_HTX + cb * 32 + q * 8, (phHT >> pb) & 1u);
                    phHT ^= 1u << pb;
                    #pragma unroll
                    for (int kk = 0; kk < 4; kk++) {
                        const int kc = q * 4 + kk;
                        uint32_t a0[4], a1[4];
                        const uint32_t ad = hbase + (kc >> 1) * BLKB + (kc & 1) * 32 + aoffB;
                        ldsm4(a0, ad);
                        ldsm4(a1, ad + 1280);
                        mma16816(acc[0][0], a0, bw[0][kc][0], bw[0][kc][1]);
                        mma16816(acc[0][1], a0, bw[1][kc][0], bw[1][kc][1]);
                        mma16816(acc[1][0], a1, bw[0][kc][0], bw[0][kc][1]);
                        mma16816(acc[1][1], a1, bw[1][kc][0], bw[1][kc][1]);
                    }
                }
            }

            // ---- shfl epilogue: pair-exchange gates, no smem round-trip ----
            #pragma unroll
            for (int mi = 0; mi < 2; mi++) {
                #pragma unroll
                for (int ni = 0; ni < 2; ni++) {
                    float sa = (tig & 1) ? acc[mi][ni][0] : acc[mi][ni][2];
                    float sb = (tig & 1) ? acc[mi][ni][1] : acc[mi][ni][3];
                    float ra = __shfl_xor_sync(0xffffffffu, sa, 1, 32);
                    float rb = __shfl_xor_sync(0xffffffffu, sb, 1, 32);
                    float pi, pf, pg, po;
                    if (tig & 1) { pi = ra;            pf = rb;
                                   pg = acc[mi][ni][2]; po = acc[mi][ni][3]; }
                    else         { pi = acc[mi][ni][0]; pf = acc[mi][ni][1];
                                   pg = ra;             po = rb; }
                    pi += breg[ni].x; pf += breg[ni].y;
                    pg += breg[ni].z; po += breg[ni].w;
                    if constexpr (IS_L0) {
                        pi += xv[mi] * wreg[ni].x;
                        pf += xv[mi] * wreg[ni].y;
                        pg += xv[mi] * wreg[ni].z;
                        po += xv[mi] * wreg[ni].w;
                    }
                    float ig = sig_hw(pi), fg = sig_hw(pf);
                    float gg = tanh_hw(pg), og = sig_hw(po);
                    float c  = fg * creg[mi][ni] + ig * gg;
                    creg[mi][ni] = c;
                    float h  = og * tanh_hw(c);

                    const int row = r0 + 16 * mi;
                    const int u   = u0 + 2 * ni;
                    __half hh = __float2half_rn(h);
                    if constexpr (IS_L0) {
                        g_y0[t][grp][ntile][row * 40 + u] = hh;
                    } else {
                        if (t + 1 < T_)
                            g_h1[nb][grp][ntile][row * 40 + u] = hh;
                    }
                    if (t == T_ - 1) {
                        size_t oidx = ((size_t)layer_idx * B_ + (b0 + row)) * H_ + j0 + u;
                        out[oidx] = h;
                        out[(size_t)2 * B_ * H_ + oidx] = c;
                    }
                }
            }

            // ---- release: per-thread counting-flag increment (R12) ----
            if (IS_L0 || t + 1 < T_)
                red_add_rel(&g_flag[L][grp][ntile][0]);
        }
    } else if (warp == 8) {
        // ================= H-COMM WARP =================
        for (int t = 0; t < T_ - 1; ++t) {
            const int nb = (t + 1) & 1;

            // arm the 4 quarter expects for buffer nb, then reconverge so
            // no lane's bulk precedes them.
            if (lane == 0) {
                #pragma unroll
                for (int q = 0; q < 4; q++)
                    mbar_expect(MB + MB_HTX + nb * 32 + q * 8, 2 * BLKB);
            }
            __syncwarp();

            // h blocks for step t+1: lane w serves producer w (self-gated:
            // the poll set includes our own CTA's flag at lane == ntile)
            if (lane < 8) {
                while (ld_acq(&g_flag[L][grp][lane][0]) <
                       (unsigned)((t + 1) << 8)) { }
                const void* src = IS_L0 ? (const void*)&g_y0[t][grp][lane][0]
                                        : (const void*)&g_h1[nb][grp][lane][0];
                bulk_g2s(smb + AS_H + (uint32_t)nb * GBUF + lane * BLKB, src,
                         BLKB, MB + MB_HTX + nb * 32 + (lane >> 1) * 8);
            }
            __syncwarp();
        }
    } else {
        // ================= Y-COMM WARP (L1 only) =================
        if constexpr (!IS_L0) {
            // prologue: arm + fetch y0[0] -> slot0, y0[1] -> slot1
            if (lane == 0) {
                mbar_expect(MB + MB_YTX + 0, GBUF);
                mbar_expect(MB + MB_YTX + 8, GBUF);
            }
            __syncwarp();
            if (lane < 8) {
                while (ld_acq(&g_flag[0][grp][lane][0]) < (1u << 8)) { }
                bulk_g2s(smb + AS_Y + lane * BLKB, &g_y0[0][grp][lane][0],
                         BLKB, MB + MB_YTX + 0);
                while (ld_acq(&g_flag[0][grp][lane][0]) < (2u << 8)) { }
                bulk_g2s(smb + AS_Y + GBUF + lane * BLKB, &g_y0[1][grp][lane][0],
                         BLKB, MB + MB_YTX + 8);
            }
            __syncwarp();

            for (int t = 0; t + 2 < T_; ++t) {
                const int slot = (t + 2) % 3;
                // self-gate on own CTA's progress (step t-1 finished) so the
                // slot being refilled was fully consumed; then arm.
                if (lane == 0) {
                    if (t > 0) {
                        while (ld_acq(&g_flag[1][grp][ntile][0]) <
                               (unsigned)(t << 8)) { }
                    }
                    mbar_expect(MB + MB_YTX + slot * 8, GBUF);
                }
                __syncwarp();
                // fetch y0[t+2] (distance-2 slack vs L0)
                if (lane < 8) {
                    while (ld_acq(&g_flag[0][grp][lane][0]) <
                           (unsigned)((t + 3) << 8)) { }
                    bulk_g2s(smb + AS_Y + (uint32_t)slot * GBUF + lane * BLKB,
                             &g_y0[t + 2][grp][lane][0], BLKB,
                             MB + MB_YTX + slot * 8);
                }
                __syncwarp();
            }
        }
    }
}

__global__ void __launch_bounds__(THREADS, 1)
lstm_fused_kernel(const float* __restrict__ x,
                  const float* __restrict__ Wih0, const float* __restrict__ Whh0,
                  const float* __restrict__ bih0, const float* __restrict__ bhh0,
                  const float* __restrict__ Wih1, const float* __restrict__ Whh1,
                  const float* __restrict__ bih1, const float* __restrict__ bhh1,
                  float* __restrict__ out) {
    if (blockIdx.z == 0)
        run_layer<true >(x, Wih0, Whh0, bih0, bhh0, out, 0);
    else
        run_layer<false>(nullptr, Wih1, Whh1, bih1, bhh1, out, 1);
}

extern "C" void kernel_launch(void* const* d_in, const int* in_sizes, int n_in,
                              void* d_out, int out_size) {
    (void)in_sizes; (void)n_in; (void)out_size;
    const float* x    = (const float*)d_in[0];
    const float* Wih0 = (const float*)d_in[1];
    const float* Whh0 = (const float*)d_in[2];
    const float* bih0 = (const float*)d_in[3];
    const float* bhh0 = (const float*)d_in[4];
    const float* Wih1 = (const float*)d_in[5];
    const float* Whh1 = (const float*)d_in[6];
    const float* bih1 = (const float*)d_in[7];
    const float* bhh1 = (const float*)d_in[8];
    float* out = (float*)d_out;

    cudaFuncSetAttribute((const void*)&lstm_fused_kernel,
                         cudaFuncAttributeMaxDynamicSharedMemorySize, SMEM_TOTAL);

    init_kernel<<<1, 128>>>();

    dim3 grid(NTILE, NGROUP, 2);
    lstm_fused_kernel<<<grid, THREADS, SMEM_TOTAL>>>(
        x, Wih0, Whh0, bih0, bhh0, Wih1, Whh1, bih1, bhh1, out);
}